// round 9
// baseline (speedup 1.0000x reference)
#include <cuda_runtime.h>
#include <cuda_bf16.h>
#include <math.h>

// Problem constants
#define B_  16
#define N_  2048
#define E_  1024
#define G_  2
#define V_  320
#define D_  512
#define GV_ 640
#define M_  (B_ * N_)
#define ROWS_ (M_ * G_)

#define THRESH 0.05f

// GEMM tiling: BM=128, BN=128, BK=64, 2-stage
#define BK   64
#define NIT  (E_ / BK)        // 16
#define APITCH 72             // bf16 elems per smem row (144 B, ldsm conflict-free)
#define A_ST_BYTES 18432      /* 128 * 72 * 2 */
#define ST_BYTES   36864      /* A + B per stage */
#define SMEM_DYN   73728      /* 2 stages */

// Device scratch (sanctioned: __device__ globals)
__device__ __nv_bfloat16 g_xb[(size_t)M_ * E_];   // x bf16
__device__ __nv_bfloat16 g_wt[(size_t)GV_ * E_];  // W^T bf16 [n][k]
__device__ __nv_bfloat16 g_hb[(size_t)M_ * GV_];  // logits bf16
__device__ int           g_counts[B_ * G_ * V_];

// ---------------------------------------------------------------------------
// PTX helpers
// ---------------------------------------------------------------------------
__device__ __forceinline__ unsigned smem_u32(const void* p) {
    unsigned a;
    asm("{ .reg .u64 t; cvta.to.shared.u64 t, %1; cvt.u32.u64 %0, t; }"
        : "=r"(a) : "l"(p));
    return a;
}
__device__ __forceinline__ void cp_async16(unsigned dst, const void* src) {
    asm volatile("cp.async.cg.shared.global [%0], [%1], 16;" :: "r"(dst), "l"(src));
}
__device__ __forceinline__ void cp_commit() {
    asm volatile("cp.async.commit_group;" ::: "memory");
}
__device__ __forceinline__ void cp_wait0() { asm volatile("cp.async.wait_group 0;" ::: "memory"); }
__device__ __forceinline__ void cp_wait1() { asm volatile("cp.async.wait_group 1;" ::: "memory"); }

__device__ __forceinline__ void ldsm4(unsigned* r, unsigned addr) {
    asm volatile("ldmatrix.sync.aligned.m8n8.x4.shared.b16 {%0,%1,%2,%3}, [%4];"
                 : "=r"(r[0]), "=r"(r[1]), "=r"(r[2]), "=r"(r[3]) : "r"(addr));
}
__device__ __forceinline__ void mma16816(float* c, const unsigned* a,
                                         unsigned b0, unsigned b1) {
    asm volatile(
        "mma.sync.aligned.m16n8k16.row.col.f32.bf16.bf16.f32 "
        "{%0,%1,%2,%3}, {%4,%5,%6,%7}, {%8,%9}, {%0,%1,%2,%3};"
        : "+f"(c[0]), "+f"(c[1]), "+f"(c[2]), "+f"(c[3])
        : "r"(a[0]), "r"(a[1]), "r"(a[2]), "r"(a[3]), "r"(b0), "r"(b1));
}

// ---------------------------------------------------------------------------
// Kernel 0: zero histograms
// ---------------------------------------------------------------------------
__global__ void zero_counts_kernel() {
    int i = blockIdx.x * blockDim.x + threadIdx.x;
    if (i < B_ * G_ * V_) g_counts[i] = 0;
}

// ---------------------------------------------------------------------------
// Kernel 1a: convert x -> bf16
// ---------------------------------------------------------------------------
__global__ __launch_bounds__(256)
void convert_x_kernel(const float* __restrict__ x) {
    int i = blockIdx.x * blockDim.x + threadIdx.x;
    const int n4 = M_ * E_ / 4;
    if (i >= n4) return;
    float4 v = ((const float4*)x)[i];
    union { __nv_bfloat16 h[4]; uint2 u; } pk;
    pk.h[0] = __float2bfloat16(v.x);
    pk.h[1] = __float2bfloat16(v.y);
    pk.h[2] = __float2bfloat16(v.z);
    pk.h[3] = __float2bfloat16(v.w);
    ((uint2*)g_xb)[i] = pk.u;
}

// ---------------------------------------------------------------------------
// Kernel 1b: transpose+convert W -> W^T bf16
// ---------------------------------------------------------------------------
__global__ __launch_bounds__(256)
void convert_w_kernel(const float* __restrict__ W) {
    int i = blockIdx.x * blockDim.x + threadIdx.x;
    if (i >= GV_ * E_) return;
    int n = i >> 10;
    int k = i & 1023;
    g_wt[i] = __float2bfloat16(W[(size_t)k * GV_ + n]);
}

// ---------------------------------------------------------------------------
// Kernel 2: bf16 mma.sync GEMM, BM=128, BN=128, BK=64, 2-stage dyn smem.
// 256 thr = 8 warps (2 x 4), warp tile 64x32. 16 barriers total (vs 32).
// Race-free order: wait -> sync -> compute -> sync -> issue next.
// ---------------------------------------------------------------------------
__device__ __forceinline__ void issue_stage64(unsigned sBase, int s, int it,
                                              int bm, int bn, int tid) {
    const unsigned stBase = sBase + (unsigned)(s * ST_BYTES);
    const int row = tid >> 1;                 // 0..127
    const int ch  = (tid & 1) * 64;           // byte offset 0 or 64 within 128B row
    const __nv_bfloat16* aSrc = g_xb + (size_t)(bm + row) * E_ + it * BK + (tid & 1) * 32;
    const __nv_bfloat16* bSrc = g_wt + (size_t)(bn + row) * E_ + it * BK + (tid & 1) * 32;
    const unsigned dstA = stBase + (unsigned)(row * 144 + ch);
    const unsigned dstB = dstA + A_ST_BYTES;
#pragma unroll
    for (int j = 0; j < 4; j++) {
        cp_async16(dstA + j * 16, aSrc + j * 8);
        cp_async16(dstB + j * 16, bSrc + j * 8);
    }
    cp_commit();
}

__global__ __launch_bounds__(256, 2)
void mma_gemm_kernel() {
    extern __shared__ __align__(16) unsigned char dsm[];

    const int tid  = threadIdx.x;
    const int lane = tid & 31;
    const int wid  = tid >> 5;
    const int bm = blockIdx.y * 128;
    const int bn = blockIdx.x * 128;
    const int wm = (wid & 1) * 64;
    const int wn = (wid >> 1) * 32;

    const unsigned sBase = smem_u32(dsm);

    float acc[4][4][4];
    for (int i = 0; i < 4; i++)
        for (int j = 0; j < 4; j++)
            for (int k = 0; k < 4; k++)
                acc[i][j][k] = 0.0f;

    // Prologue: both stages
    issue_stage64(sBase, 0, 0, bm, bn, tid);
    issue_stage64(sBase, 1, 1, bm, bn, tid);

    // ldsm lane addressing (pitch 72 elems = 144 B)
    const int arow_f = wm + (lane & 15);
    const int acol_f = (lane >> 4) * 8;
    const unsigned aOff = (unsigned)(arow_f * APITCH + acol_f) * 2u;
    const int brow_f = wn + (lane & 7) + ((lane >> 4) << 3);
    const int bcol_f = ((lane >> 3) & 1) * 8;
    const unsigned bOff = (unsigned)(brow_f * APITCH + bcol_f) * 2u + (unsigned)A_ST_BYTES;

    for (int it = 0; it < NIT; ++it) {
        const int s = it & 1;
        if (it < NIT - 1) cp_wait1(); else cp_wait0();
        __syncthreads();

        const unsigned so = sBase + (unsigned)(s * ST_BYTES);
        const unsigned aB = so + aOff;
        const unsigned bB = so + bOff;
#pragma unroll
        for (int kk = 0; kk < 4; ++kk) {
            unsigned af[4][4];
            unsigned bf[2][4];
#pragma unroll
            for (int mi = 0; mi < 4; ++mi)
                ldsm4(af[mi], aB + (unsigned)(mi * 16 * APITCH + kk * 16) * 2u);
#pragma unroll
            for (int p = 0; p < 2; ++p)
                ldsm4(bf[p], bB + (unsigned)(p * 16 * APITCH + kk * 16) * 2u);
#pragma unroll
            for (int mi = 0; mi < 4; ++mi) {
#pragma unroll
                for (int p = 0; p < 2; ++p) {
                    mma16816(acc[mi][2 * p],     af[mi], bf[p][0], bf[p][1]);
                    mma16816(acc[mi][2 * p + 1], af[mi], bf[p][2], bf[p][3]);
                }
            }
        }
        __syncthreads();

        if (it + 2 < NIT)
            issue_stage64(sBase, s, it + 2, bm, bn, tid);
    }

    // Epilogue: f32 acc -> bf16 stores to g_hb
    const int cg = lane >> 2;
    const int tg = lane & 3;
#pragma unroll
    for (int mi = 0; mi < 4; ++mi) {
        const int row = bm + wm + mi * 16 + cg;
        __nv_bfloat162* o0 =
            (__nv_bfloat162*)(g_hb + (size_t)row * GV_ + bn + wn + tg * 2);
        __nv_bfloat162* o1 =
            (__nv_bfloat162*)(g_hb + (size_t)(row + 8) * GV_ + bn + wn + tg * 2);
#pragma unroll
        for (int ni = 0; ni < 4; ++ni) {
            float2 v0; v0.x = acc[mi][ni][0]; v0.y = acc[mi][ni][1];
            float2 v1; v1.x = acc[mi][ni][2]; v1.y = acc[mi][ni][3];
            o0[ni * 4] = __float22bfloat162_rn(v0);
            o1[ni * 4] = __float22bfloat162_rn(v1);
        }
    }
}

// ---------------------------------------------------------------------------
// Kernel 3: argmax + exact rescue + histogram + gather. One warp per row.
// ---------------------------------------------------------------------------
__global__ __launch_bounds__(256)
void argmax_gather_kernel(const float* __restrict__ x,
                          const float* __restrict__ u,
                          const float* __restrict__ W,
                          const float* __restrict__ bias,
                          const float* __restrict__ codebook,
                          float* __restrict__ out) {
    const int warp = (blockIdx.x * blockDim.x + threadIdx.x) >> 5;
    const int lane = threadIdx.x & 31;
    if (warp >= ROWS_) return;

    const int r    = warp;
    const int gidx = r & 1;
    const __nv_bfloat16* hrow = g_hb + (size_t)r * V_;
    const float* urow = u + (size_t)r * V_;
    const float* brow = bias + gidx * V_;

    const float kA = 1.0f - 2.0f * 1e-7f;
    const float kB = 1e-7f;

    float vals[10];
    float best = -3.4e38f;
    int   bi   = 0;
#pragma unroll
    for (int i = 0; i < 10; i++) {
        const int v = i * 32 + lane;
        float uu = fmaf(urow[v], kA, kB);
        float gn = -logf(-logf(uu));
        float val = __bfloat162float(hrow[v]) + brow[v] + gn;
        vals[i] = val;
        if (val > best) { best = val; bi = v; }
    }
#pragma unroll
    for (int off = 16; off; off >>= 1) {
        float ov = __shfl_down_sync(0xffffffffu, best, off);
        int   oi = __shfl_down_sync(0xffffffffu, bi, off);
        if (ov > best || (ov == best && oi < bi)) { best = ov; bi = oi; }
    }
    best = __shfl_sync(0xffffffffu, best, 0);
    bi   = __shfl_sync(0xffffffffu, bi, 0);

    float second = -3.4e38f;
#pragma unroll
    for (int i = 0; i < 10; i++) {
        const int v = i * 32 + lane;
        if (v != bi) second = fmaxf(second, vals[i]);
    }
#pragma unroll
    for (int off = 16; off; off >>= 1)
        second = fmaxf(second, __shfl_xor_sync(0xffffffffu, second, off));

    if (best - second < THRESH) {
        const float* xrow = x + (size_t)(r >> 1) * E_;
        float ex_best = -3.4e38f;
        int   ex_bi   = V_;
        const float cut = best - THRESH;
        for (int i = 0; i < 10; i++) {
            unsigned bal = __ballot_sync(0xffffffffu, vals[i] >= cut);
            while (bal) {
                const int j = __ffs(bal) - 1;
                bal &= bal - 1;
                const int vc = i * 32 + j;
                const int c  = gidx * V_ + vc;
                float s = 0.0f;
                for (int k = lane; k < E_; k += 32)
                    s = fmaf(xrow[k], W[(size_t)k * GV_ + c], s);
#pragma unroll
                for (int off = 16; off; off >>= 1)
                    s += __shfl_xor_sync(0xffffffffu, s, off);
                float uu = fmaf(urow[vc], kA, kB);
                float ex = s + brow[vc] + (-logf(-logf(uu)));
                if (ex > ex_best || (ex == ex_best && vc < ex_bi)) {
                    ex_best = ex;
                    ex_bi   = vc;
                }
            }
        }
        bi = ex_bi;
    }

    if (lane == 0) {
        int b = r >> 12;
        atomicAdd(&g_counts[(b * G_ + gidx) * V_ + bi], 1);
    }

    const float4* cb = (const float4*)(codebook + ((size_t)(gidx * V_ + bi)) * D_);
    float4*       op = (float4*)(out + (size_t)r * D_);
#pragma unroll
    for (int i = 0; i < 4; i++)
        op[i * 32 + lane] = cb[i * 32 + lane];
}

// ---------------------------------------------------------------------------
// Kernel 4: entropy from histograms
// ---------------------------------------------------------------------------
__global__ void entropy_kernel(float* __restrict__ out, int out_size) {
    const int w    = threadIdx.x >> 5;
    const int lane = threadIdx.x & 31;
    const int* c = g_counts + w * V_;

    float cv[10];
    float m = -3.4e38f;
#pragma unroll
    for (int i = 0; i < 10; i++) {
        cv[i] = (float)c[lane + i * 32];
        m = fmaxf(m, cv[i]);
    }
#pragma unroll
    for (int off = 16; off; off >>= 1)
        m = fmaxf(m, __shfl_xor_sync(0xffffffffu, m, off));

    float s = 0.0f;
#pragma unroll
    for (int i = 0; i < 10; i++)
        s += expf(cv[i] - m);
#pragma unroll
    for (int off = 16; off; off >>= 1)
        s += __shfl_xor_sync(0xffffffffu, s, off);

    float ent = 0.0f;
#pragma unroll
    for (int i = 0; i < 10; i++) {
        float p = expf(cv[i] - m) / s;
        ent += p * logf(p + 1e-8f);
    }
#pragma unroll
    for (int off = 16; off; off >>= 1)
        ent += __shfl_xor_sync(0xffffffffu, ent, off);

    __shared__ float part[32];
    if (lane == 0) part[w] = ent;
    __syncthreads();
    if (threadIdx.x == 0) {
        float t = 0.0f;
#pragma unroll
        for (int i = 0; i < 32; i++)
            t += part[i];
        out[out_size - 1] = -t / (float)(G_ * V_);
    }
}

// ---------------------------------------------------------------------------
extern "C" void kernel_launch(void* const* d_in, const int* in_sizes, int n_in,
                              void* d_out, int out_size) {
    const float* x        = (const float*)d_in[0];
    const float* u        = (const float*)d_in[1];
    const float* W        = (const float*)d_in[2];
    const float* bias     = (const float*)d_in[3];
    const float* codebook = (const float*)d_in[4];
    float* out = (float*)d_out;
    (void)in_sizes; (void)n_in;

    cudaFuncSetAttribute(mma_gemm_kernel,
                         cudaFuncAttributeMaxDynamicSharedMemorySize, SMEM_DYN);

    zero_counts_kernel<<<(B_ * G_ * V_ + 255) / 256, 256>>>();

    convert_x_kernel<<<(M_ * E_ / 4 + 255) / 256, 256>>>(x);
    convert_w_kernel<<<(GV_ * E_ + 255) / 256, 256>>>(W);

    dim3 gg(GV_ / 128, M_ / 128);   // (5, 256)
    mma_gemm_kernel<<<gg, 256, SMEM_DYN>>>();

    argmax_gather_kernel<<<(ROWS_ * 32 + 255) / 256, 256>>>(x, u, W, bias, codebook, out);

    entropy_kernel<<<1, 1024>>>(out, out_size);
}